// round 2
// baseline (speedup 1.0000x reference)
#include <cuda_runtime.h>
#include <cuda_bf16.h>

// Problem constants (fixed by setup_inputs)
#define C_DIM   192
#define NHEADS  6
#define HDIM    32
#define WS2     64          // 8x8 window
#define NWIN    4096        // 4 * 32 * 32
#define MTOK    262144      // 4 * 256 * 256
#define QKV_N   576         // 3 * 192
#define SCALE_Q 0.17677669529663687f   // 32^-0.5

// Scratch (device globals: allocation-free per harness rules)
__device__ float g_q [NWIN * NHEADS * WS2 * HDIM];   // [win][head][pos][d]
__device__ float g_k [NWIN * NHEADS * WS2 * HDIM];
__device__ float g_v [NWIN * NHEADS * WS2 * HDIM];
__device__ float g_ao[MTOK * C_DIM];                 // [win*64+pos][C]

// ---------------------------------------------------------------------------
// Kernel 1: QKV projection GEMM  y[m,n] = sum_k x[m,k] * qkv_w[n,k]
// Tile 128x64, BK=16, 256 threads, 8x4 per thread, register-prefetch pipeline.
// Epilogue scatters into window layout, scales q.
// ---------------------------------------------------------------------------
__global__ __launch_bounds__(256) void qkv_kernel(const float* __restrict__ X,
                                                  const float* __restrict__ W)
{
    __shared__ float As[16][128];
    __shared__ float Bs[16][64];

    const int tid = threadIdx.x;
    const int tx = tid & 15;        // 0..15 -> 4 cols each
    const int ty = tid >> 4;        // 0..15 -> 8 rows each
    const int rowBase = blockIdx.y << 7;   // M tile
    const int colBase = blockIdx.x << 6;   // N tile

    float acc[8][4];
#pragma unroll
    for (int i = 0; i < 8; i++)
#pragma unroll
        for (int j = 0; j < 4; j++) acc[i][j] = 0.f;

    // global-load assignments
    const int aRow = tid >> 1;            // 0..127
    const int aKg  = (tid & 1) * 2;       // float4 group 0 or 2 (loads kg, kg+1)
    const int bRow = tid >> 2;            // 0..63
    const int bKg  = tid & 3;             // float4 group 0..3

    const float* Aptr = X + (size_t)(rowBase + aRow) * C_DIM + aKg * 4;
    const float* Bptr = W + (size_t)(colBase + bRow) * C_DIM + bKg * 4;

    // prefetch first K-tile
    float4 av0 = *(const float4*)(Aptr + 0);
    float4 av1 = *(const float4*)(Aptr + 4);
    float4 bv  = *(const float4*)(Bptr + 0);

    for (int k0 = 0; k0 < C_DIM; k0 += 16) {
        __syncthreads();
        As[aKg * 4 + 0][aRow] = av0.x;
        As[aKg * 4 + 1][aRow] = av0.y;
        As[aKg * 4 + 2][aRow] = av0.z;
        As[aKg * 4 + 3][aRow] = av0.w;
        As[aKg * 4 + 4][aRow] = av1.x;
        As[aKg * 4 + 5][aRow] = av1.y;
        As[aKg * 4 + 6][aRow] = av1.z;
        As[aKg * 4 + 7][aRow] = av1.w;
        Bs[bKg * 4 + 0][bRow] = bv.x;
        Bs[bKg * 4 + 1][bRow] = bv.y;
        Bs[bKg * 4 + 2][bRow] = bv.z;
        Bs[bKg * 4 + 3][bRow] = bv.w;
        __syncthreads();

        // issue next tile's global loads BEFORE compute (latency overlap)
        if (k0 + 16 < C_DIM) {
            av0 = *(const float4*)(Aptr + k0 + 16);
            av1 = *(const float4*)(Aptr + k0 + 20);
            bv  = *(const float4*)(Bptr + k0 + 16);
        }

#pragma unroll
        for (int kk = 0; kk < 16; kk++) {
            float4 a0 = *(const float4*)&As[kk][ty * 8];
            float4 a1 = *(const float4*)&As[kk][ty * 8 + 4];
            float4 b4 = *(const float4*)&Bs[kk][tx * 4];
            float av[8] = {a0.x, a0.y, a0.z, a0.w, a1.x, a1.y, a1.z, a1.w};
            float bb[4] = {b4.x, b4.y, b4.z, b4.w};
#pragma unroll
            for (int i = 0; i < 8; i++)
#pragma unroll
                for (int j = 0; j < 4; j++)
                    acc[i][j] = fmaf(av[i], bb[j], acc[i][j]);
        }
    }

    // Epilogue: scatter to window layout
    const int part = colBase / C_DIM;                 // 0=q,1=k,2=v (64 | 192)
    const int crem = (colBase % C_DIM) + tx * 4;      // 0..191
    const int head = crem >> 5;
    const int d0   = crem & 31;
    float* dst = (part == 0) ? g_q : (part == 1) ? g_k : g_v;
    const float mult = (part == 0) ? SCALE_Q : 1.f;

#pragma unroll
    for (int i = 0; i < 8; i++) {
        int m  = rowBase + ty * 8 + i;
        int b  = m >> 16;
        int hw = m & 65535;
        int h  = hw >> 8;
        int w  = hw & 255;
        int win = ((((b << 5) | (h >> 3)) << 5) | (w >> 3));
        int pos = ((h & 7) << 3) | (w & 7);
        size_t idx = (size_t)(win * NHEADS + head) * (WS2 * HDIM) + pos * HDIM + d0;
        float4 o;
        o.x = acc[i][0] * mult;
        o.y = acc[i][1] * mult;
        o.z = acc[i][2] * mult;
        o.w = acc[i][3] * mult;
        *(float4*)&dst[idx] = o;
    }
}

// ---------------------------------------------------------------------------
// Kernel 2: per-(window, head) attention. 64 threads, 1 query row per thread.
// ---------------------------------------------------------------------------
__global__ __launch_bounds__(64) void attn_kernel(const float* __restrict__ rpb)
{
    __shared__ float k_s[64][32];
    __shared__ float v_s[64][32];
    __shared__ float p_s[64][65];     // +1 pad: conflict-free rows
    __shared__ float bias_s[232];     // 225 used

    const int win  = blockIdx.x;
    const int head = blockIdx.y;
    const int tid  = threadIdx.x;

    const size_t base = (size_t)(win * NHEADS + head) * (WS2 * HDIM);

    // Cooperative K/V load (fully coalesced float4)
    const float4* kg4 = (const float4*)(g_k + base);
    const float4* vg4 = (const float4*)(g_v + base);
    float4* ks4 = (float4*)&k_s[0][0];
    float4* vs4 = (float4*)&v_s[0][0];
#pragma unroll
    for (int i = 0; i < 8; i++) {
        ks4[i * 64 + tid] = kg4[i * 64 + tid];
        vs4[i * 64 + tid] = vg4[i * 64 + tid];
    }
    for (int i = tid; i < 225; i += 64) bias_s[i] = rpb[i * NHEADS + head];

    // Own query row into registers (one full 128B line per thread)
    float q[32];
    const float4* qg4 = (const float4*)(g_q + base + tid * HDIM);
#pragma unroll
    for (int i = 0; i < 8; i++) {
        float4 t = qg4[i];
        q[i * 4 + 0] = t.x; q[i * 4 + 1] = t.y;
        q[i * 4 + 2] = t.z; q[i * 4 + 3] = t.w;
    }
    __syncthreads();

    const int qy = tid >> 3, qx = tid & 7;

    float maxv = -1e30f;
#pragma unroll 4
    for (int j = 0; j < 64; j++) {
        float dot = 0.f;
#pragma unroll
        for (int d = 0; d < 32; d++) dot = fmaf(q[d], k_s[j][d], dot);
        int dy = qy - (j >> 3) + 7;
        int dx = qx - (j & 7) + 7;
        float s = dot + bias_s[dy * 15 + dx];
        p_s[tid][j] = s;
        maxv = fmaxf(maxv, s);
    }

    float sum = 0.f;
#pragma unroll
    for (int j = 0; j < 64; j++) {
        float e = __expf(p_s[tid][j] - maxv);
        p_s[tid][j] = e;
        sum += e;
    }
    const float inv = 1.f / sum;

    float acc[32];
#pragma unroll
    for (int d = 0; d < 32; d++) acc[d] = 0.f;
#pragma unroll 4
    for (int j = 0; j < 64; j++) {
        float p = p_s[tid][j];
#pragma unroll
        for (int d = 0; d < 32; d++) acc[d] = fmaf(p, v_s[j][d], acc[d]);
    }

    float* dst = g_ao + ((size_t)win * WS2 + tid) * C_DIM + head * HDIM;
#pragma unroll
    for (int i = 0; i < 8; i++) {
        float4 o;
        o.x = acc[i * 4 + 0] * inv;
        o.y = acc[i * 4 + 1] * inv;
        o.z = acc[i * 4 + 2] * inv;
        o.w = acc[i * 4 + 3] * inv;
        *(float4*)&dst[i * 4] = o;
    }
}

// ---------------------------------------------------------------------------
// Kernel 3: output projection GEMM + bias, un-windowing scatter epilogue.
// Same pipelined 128x64 tile structure as kernel 1.
// ---------------------------------------------------------------------------
__global__ __launch_bounds__(256) void proj_kernel(const float* __restrict__ W,
                                                   const float* __restrict__ bias,
                                                   float* __restrict__ out)
{
    __shared__ float As[16][128];
    __shared__ float Bs[16][64];

    const int tid = threadIdx.x;
    const int tx = tid & 15;
    const int ty = tid >> 4;
    const int rowBase = blockIdx.y << 7;
    const int colBase = blockIdx.x << 6;

    float acc[8][4];
#pragma unroll
    for (int i = 0; i < 8; i++)
#pragma unroll
        for (int j = 0; j < 4; j++) acc[i][j] = 0.f;

    const int aRow = tid >> 1;
    const int aKg  = (tid & 1) * 2;
    const int bRow = tid >> 2;
    const int bKg  = tid & 3;

    const float* Aptr = g_ao + (size_t)(rowBase + aRow) * C_DIM + aKg * 4;
    const float* Bptr = W    + (size_t)(colBase + bRow) * C_DIM + bKg * 4;

    float4 av0 = *(const float4*)(Aptr + 0);
    float4 av1 = *(const float4*)(Aptr + 4);
    float4 bv  = *(const float4*)(Bptr + 0);

    for (int k0 = 0; k0 < C_DIM; k0 += 16) {
        __syncthreads();
        As[aKg * 4 + 0][aRow] = av0.x;
        As[aKg * 4 + 1][aRow] = av0.y;
        As[aKg * 4 + 2][aRow] = av0.z;
        As[aKg * 4 + 3][aRow] = av0.w;
        As[aKg * 4 + 4][aRow] = av1.x;
        As[aKg * 4 + 5][aRow] = av1.y;
        As[aKg * 4 + 6][aRow] = av1.z;
        As[aKg * 4 + 7][aRow] = av1.w;
        Bs[bKg * 4 + 0][bRow] = bv.x;
        Bs[bKg * 4 + 1][bRow] = bv.y;
        Bs[bKg * 4 + 2][bRow] = bv.z;
        Bs[bKg * 4 + 3][bRow] = bv.w;
        __syncthreads();

        if (k0 + 16 < C_DIM) {
            av0 = *(const float4*)(Aptr + k0 + 16);
            av1 = *(const float4*)(Aptr + k0 + 20);
            bv  = *(const float4*)(Bptr + k0 + 16);
        }

#pragma unroll
        for (int kk = 0; kk < 16; kk++) {
            float4 a0 = *(const float4*)&As[kk][ty * 8];
            float4 a1 = *(const float4*)&As[kk][ty * 8 + 4];
            float4 b4 = *(const float4*)&Bs[kk][tx * 4];
            float av[8] = {a0.x, a0.y, a0.z, a0.w, a1.x, a1.y, a1.z, a1.w};
            float bb[4] = {b4.x, b4.y, b4.z, b4.w};
#pragma unroll
            for (int i = 0; i < 8; i++)
#pragma unroll
                for (int j = 0; j < 4; j++)
                    acc[i][j] = fmaf(av[i], bb[j], acc[i][j]);
        }
    }

    const int n0 = colBase + tx * 4;
    const float4 bv4 = *(const float4*)&bias[n0];

#pragma unroll
    for (int i = 0; i < 8; i++) {
        int mp  = rowBase + ty * 8 + i;        // window-ordered token id
        int win = mp >> 6;
        int pos = mp & 63;
        int b   = win >> 10;
        int wr  = win & 1023;
        int wh  = wr >> 5;
        int ww  = wr & 31;
        int h   = (wh << 3) | (pos >> 3);
        int w   = (ww << 3) | (pos & 7);
        size_t oidx = ((size_t)((b << 16) | (h << 8) | w)) * C_DIM + n0;
        float4 o;
        o.x = acc[i][0] + bv4.x;
        o.y = acc[i][1] + bv4.y;
        o.z = acc[i][2] + bv4.z;
        o.w = acc[i][3] + bv4.w;
        *(float4*)&out[oidx] = o;
    }
}

// ---------------------------------------------------------------------------
extern "C" void kernel_launch(void* const* d_in, const int* in_sizes, int n_in,
                              void* d_out, int out_size)
{
    const float* x      = (const float*)d_in[0];
    const float* qkv_w  = (const float*)d_in[1];
    const float* proj_w = (const float*)d_in[2];
    const float* proj_b = (const float*)d_in[3];
    const float* rpb    = (const float*)d_in[4];
    float* out = (float*)d_out;

    // QKV: M=262144 (2048 tiles of 128), N=576 (9 tiles of 64)
    qkv_kernel<<<dim3(QKV_N / 64, MTOK / 128), 256>>>(x, qkv_w);

    // Attention: one block per (window, head)
    attn_kernel<<<dim3(NWIN, NHEADS), 64>>>(rpb);

    // Projection: N=192 (3 tiles of 64)
    proj_kernel<<<dim3(C_DIM / 64, MTOK / 128), 256>>>(proj_w, proj_b, out);
}